// round 7
// baseline (speedup 1.0000x reference)
#include <cuda_runtime.h>
#include <cuda_bf16.h>

// Snack: out[p] = tanh((f[i]-f[j])^T M (f[i]-f[j])), P = 8,388,608, 20 AAs.
// Fused persistent kernel:
//   - factorized table build: G = (F M) F^T; dist = G[ii]-G[ij]-G[ji]+G[jj]
//   - software-pipelined 2-wide prefetch-1 gather (4 LDG.128 in flight),
//     low register footprint -> 6 CTAs/SM (75% occ).
// Traffic floor: 12 B/pair = 100.7 MB -> ~13-14us practical.

#define NUM_AA   20
#define FEAT_DIM 16
#define FPAD     17
#define TBL      (NUM_AA * NUM_AA)
#define THREADS  256
#define NF       (NUM_AA * FEAT_DIM)   // 320

__global__ __launch_bounds__(THREADS, 6) void snack_fused_kernel(
    const float*  __restrict__ features,   // [20, 16]
    const float*  __restrict__ M,          // [16, 16]
    const int4*   __restrict__ idx_i4,     // [P/4]
    const int4*   __restrict__ idx_j4,     // [P/4]
    float4*       __restrict__ out4,       // [P/4]
    int n4)
{
    __shared__ float s_F[NUM_AA * FPAD];
    __shared__ float s_M[FEAT_DIM * FEAT_DIM];
    __shared__ float s_FM[NUM_AA * FPAD];
    __shared__ float s_tbl[TBL];

    const int t = threadIdx.x;

    for (int k = t; k < NF; k += THREADS) {
        const int r = k >> 4, c = k & 15;
        s_F[r * FPAD + c] = features[k];
    }
    for (int k = t; k < FEAT_DIM * FEAT_DIM; k += THREADS) s_M[k] = M[k];
    __syncthreads();

    for (int k = t; k < NF; k += THREADS) {
        const int r = k >> 4, c = k & 15;
        float acc = 0.0f;
#pragma unroll
        for (int y = 0; y < FEAT_DIM; y++)
            acc = fmaf(s_F[r * FPAD + y], s_M[y * FEAT_DIM + c], acc);
        s_FM[r * FPAD + c] = acc;
    }
    __syncthreads();

    for (int e = t; e < TBL; e += THREADS) {
        const int i = e / NUM_AA;
        const int j = e % NUM_AA;
        float gii = 0.0f, gij = 0.0f, gji = 0.0f, gjj = 0.0f;
#pragma unroll
        for (int y = 0; y < FEAT_DIM; y++) {
            const float fiy  = s_F[i * FPAD + y];
            const float fjy  = s_F[j * FPAD + y];
            const float fmiy = s_FM[i * FPAD + y];
            const float fmjy = s_FM[j * FPAD + y];
            gii = fmaf(fmiy, fiy, gii);
            gij = fmaf(fmiy, fjy, gij);
            gji = fmaf(fmjy, fiy, gji);
            gjj = fmaf(fmjy, fjy, gjj);
        }
        s_tbl[e] = tanhf(gii - gij - gji + gjj);
    }
    __syncthreads();

    // ── Software-pipelined gather: 2-wide, prefetch one iteration ahead. ──
    const int stride  = gridDim.x * THREADS;
    const int stride2 = 2 * stride;
    int p = blockIdx.x * THREADS + t;

    int4 a0, b0, a1, b1;
    bool have0 = p < n4;
    bool have1 = p + stride < n4;
    if (have0) { a0 = idx_i4[p];          b0 = idx_j4[p]; }
    if (have1) { a1 = idx_i4[p + stride]; b1 = idx_j4[p + stride]; }

    while (have0) {
        const int pn = p + stride2;
        const bool h2 = pn < n4;
        const bool h3 = pn + stride < n4;
        int4 a2, b2, a3, b3;
        if (h2) { a2 = idx_i4[pn];          b2 = idx_j4[pn]; }
        if (h3) { a3 = idx_i4[pn + stride]; b3 = idx_j4[pn + stride]; }

        {
            float4 o;
            o.x = s_tbl[a0.x * NUM_AA + b0.x];
            o.y = s_tbl[a0.y * NUM_AA + b0.y];
            o.z = s_tbl[a0.z * NUM_AA + b0.z];
            o.w = s_tbl[a0.w * NUM_AA + b0.w];
            out4[p] = o;
        }
        if (have1) {
            float4 o;
            o.x = s_tbl[a1.x * NUM_AA + b1.x];
            o.y = s_tbl[a1.y * NUM_AA + b1.y];
            o.z = s_tbl[a1.z * NUM_AA + b1.z];
            o.w = s_tbl[a1.w * NUM_AA + b1.w];
            out4[p + stride] = o;
        }

        a0 = a2; b0 = b2; a1 = a3; b1 = b3;
        have0 = h2; have1 = h3;
        p = pn;
    }
}

extern "C" void kernel_launch(void* const* d_in, const int* in_sizes, int n_in,
                              void* d_out, int out_size)
{
    const float* features = (const float*)d_in[0];   // [20,16]
    const float* M        = (const float*)d_in[1];   // [16,16]
    const int*   idx_i    = (const int*)d_in[2];     // [P]
    const int*   idx_j    = (const int*)d_in[3];     // [P]
    float*       out      = (float*)d_out;           // [P]

    const int P  = out_size;   // 8,388,608
    const int n4 = P / 4;      // 2,097,152

    static int blocks = 0;
    if (blocks == 0) {
        int per_sm = 0;
        cudaOccupancyMaxActiveBlocksPerMultiprocessor(
            &per_sm, snack_fused_kernel, THREADS, 0);
        if (per_sm < 1) per_sm = 1;
        int sms = 0;
        cudaDeviceGetAttribute(&sms, cudaDevAttrMultiProcessorCount, 0);
        if (sms <= 0) sms = 148;
        blocks = per_sm * sms;
        int max_blocks = (n4 + THREADS - 1) / THREADS;
        if (blocks > max_blocks) blocks = max_blocks;
    }

    snack_fused_kernel<<<blocks, THREADS>>>(
        features, M,
        (const int4*)idx_i, (const int4*)idx_j,
        (float4*)out, n4);
}

// round 8
// speedup vs baseline: 1.1068x; 1.1068x over previous
#include <cuda_runtime.h>
#include <cuda_bf16.h>

// Snack: out[p] = tanh((f[i]-f[j])^T M (f[i]-f[j])), P = 8,388,608, 20 AAs.
// Fused persistent kernel:
//   - factorized table build: G = (F M) F^T; dist = G[ii]-G[ij]-G[ji]+G[jj]
//   - 8-way bank-replicated tanh table: lane c=tid&7 reads copy c at
//     addr e*8+c -> copy classes occupy disjoint bank sets, conflict
//     degree drops from ~4.4 to ~2.
//   - R6-style batched ILP-4 gather (8 LDG.128 in flight per thread).
// Traffic floor: 12 B/pair = 100.7 MB -> ~13-14us practical.

#define NUM_AA   20
#define FEAT_DIM 16
#define FPAD     17
#define TBL      (NUM_AA * NUM_AA)
#define REP      8
#define THREADS  256
#define NF       (NUM_AA * FEAT_DIM)   // 320

__global__ __launch_bounds__(THREADS, 6) void snack_fused_kernel(
    const float*  __restrict__ features,   // [20, 16]
    const float*  __restrict__ M,          // [16, 16]
    const int4*   __restrict__ idx_i4,     // [P/4]
    const int4*   __restrict__ idx_j4,     // [P/4]
    float4*       __restrict__ out4,       // [P/4]
    int n4)
{
    __shared__ float s_F[NUM_AA * FPAD];
    __shared__ float s_M[FEAT_DIM * FEAT_DIM];
    __shared__ float s_FM[NUM_AA * FPAD];
    __shared__ float s_tbl[TBL * REP];     // 12.8 KB, 8-way replicated

    const int t = threadIdx.x;

    for (int k = t; k < NF; k += THREADS) {
        const int r = k >> 4, c = k & 15;
        s_F[r * FPAD + c] = features[k];
    }
    for (int k = t; k < FEAT_DIM * FEAT_DIM; k += THREADS) s_M[k] = M[k];
    __syncthreads();

    for (int k = t; k < NF; k += THREADS) {
        const int r = k >> 4, c = k & 15;
        float acc = 0.0f;
#pragma unroll
        for (int y = 0; y < FEAT_DIM; y++)
            acc = fmaf(s_F[r * FPAD + y], s_M[y * FEAT_DIM + c], acc);
        s_FM[r * FPAD + c] = acc;
    }
    __syncthreads();

    for (int e = t; e < TBL; e += THREADS) {
        const int i = e / NUM_AA;
        const int j = e % NUM_AA;
        float gii = 0.0f, gij = 0.0f, gji = 0.0f, gjj = 0.0f;
#pragma unroll
        for (int y = 0; y < FEAT_DIM; y++) {
            const float fiy  = s_F[i * FPAD + y];
            const float fjy  = s_F[j * FPAD + y];
            const float fmiy = s_FM[i * FPAD + y];
            const float fmjy = s_FM[j * FPAD + y];
            gii = fmaf(fmiy, fiy, gii);
            gij = fmaf(fmiy, fjy, gij);
            gji = fmaf(fmjy, fiy, gji);
            gjj = fmaf(fmjy, fjy, gjj);
        }
        const float v = tanhf(gii - gij - gji + gjj);
#pragma unroll
        for (int c = 0; c < REP; c++) s_tbl[e * REP + c] = v;
    }
    __syncthreads();

    // Batched ILP-4 gather: 8 independent LDG.128 in flight, then LDS+STG.
    const int lane8  = t & 7;                 // replica selector
    const int stride = gridDim.x * THREADS;
    int p = blockIdx.x * THREADS + t;

#define LOOKUP(av, bv) s_tbl[((av) * NUM_AA + (bv)) * REP + lane8]

    for (; p + 3 * stride < n4; p += 4 * stride) {
        int4 a0 = idx_i4[p];
        int4 a1 = idx_i4[p + stride];
        int4 a2 = idx_i4[p + 2 * stride];
        int4 a3 = idx_i4[p + 3 * stride];
        int4 b0 = idx_j4[p];
        int4 b1 = idx_j4[p + stride];
        int4 b2 = idx_j4[p + 2 * stride];
        int4 b3 = idx_j4[p + 3 * stride];
        float4 o;
        o.x = LOOKUP(a0.x, b0.x);
        o.y = LOOKUP(a0.y, b0.y);
        o.z = LOOKUP(a0.z, b0.z);
        o.w = LOOKUP(a0.w, b0.w);
        out4[p] = o;
        o.x = LOOKUP(a1.x, b1.x);
        o.y = LOOKUP(a1.y, b1.y);
        o.z = LOOKUP(a1.z, b1.z);
        o.w = LOOKUP(a1.w, b1.w);
        out4[p + stride] = o;
        o.x = LOOKUP(a2.x, b2.x);
        o.y = LOOKUP(a2.y, b2.y);
        o.z = LOOKUP(a2.z, b2.z);
        o.w = LOOKUP(a2.w, b2.w);
        out4[p + 2 * stride] = o;
        o.x = LOOKUP(a3.x, b3.x);
        o.y = LOOKUP(a3.y, b3.y);
        o.z = LOOKUP(a3.z, b3.z);
        o.w = LOOKUP(a3.w, b3.w);
        out4[p + 3 * stride] = o;
    }
    for (; p < n4; p += stride) {
        int4 a = idx_i4[p];
        int4 b = idx_j4[p];
        float4 o;
        o.x = LOOKUP(a.x, b.x);
        o.y = LOOKUP(a.y, b.y);
        o.z = LOOKUP(a.z, b.z);
        o.w = LOOKUP(a.w, b.w);
        out4[p] = o;
    }
#undef LOOKUP
}

extern "C" void kernel_launch(void* const* d_in, const int* in_sizes, int n_in,
                              void* d_out, int out_size)
{
    const float* features = (const float*)d_in[0];   // [20,16]
    const float* M        = (const float*)d_in[1];   // [16,16]
    const int*   idx_i    = (const int*)d_in[2];     // [P]
    const int*   idx_j    = (const int*)d_in[3];     // [P]
    float*       out      = (float*)d_out;           // [P]

    const int P  = out_size;   // 8,388,608
    const int n4 = P / 4;      // 2,097,152

    static int blocks = 0;
    if (blocks == 0) {
        int per_sm = 0;
        cudaOccupancyMaxActiveBlocksPerMultiprocessor(
            &per_sm, snack_fused_kernel, THREADS, 0);
        if (per_sm < 1) per_sm = 1;
        int sms = 0;
        cudaDeviceGetAttribute(&sms, cudaDevAttrMultiProcessorCount, 0);
        if (sms <= 0) sms = 148;
        blocks = per_sm * sms;
        int max_blocks = (n4 + THREADS - 1) / THREADS;
        if (blocks > max_blocks) blocks = max_blocks;
    }

    snack_fused_kernel<<<blocks, THREADS>>>(
        features, M,
        (const int4*)idx_i, (const int4*)idx_j,
        (float4*)out, n4);
}

// round 9
// speedup vs baseline: 1.1199x; 1.0118x over previous
#include <cuda_runtime.h>
#include <cuda_bf16.h>

// Snack: out[p] = tanh((f[i]-f[j])^T M (f[i]-f[j])), P = 8,388,608, 20 AAs.
// Fused persistent kernel:
//   - factorized table build: G = (F M) F^T; dist = G[ii]-G[ij]-G[ji]+G[jj]
//   - plain 400-entry smem table (replication proven neutral in R8)
//   - ILP-2 batched gather with a tight register budget so 8 CTAs/SM fit
//     (64 warps -> 100% theoretical occupancy; latency-bound fix).
// Traffic floor: 12 B/pair = 100.7 MB.

#define NUM_AA   20
#define FEAT_DIM 16
#define FPAD     17
#define TBL      (NUM_AA * NUM_AA)
#define THREADS  256
#define NF       (NUM_AA * FEAT_DIM)   // 320

__global__ __launch_bounds__(THREADS, 8) void snack_fused_kernel(
    const float*  __restrict__ features,   // [20, 16]
    const float*  __restrict__ M,          // [16, 16]
    const int4*   __restrict__ idx_i4,     // [P/4]
    const int4*   __restrict__ idx_j4,     // [P/4]
    float4*       __restrict__ out4,       // [P/4]
    int n4)
{
    __shared__ float s_F[NUM_AA * FPAD];
    __shared__ float s_M[FEAT_DIM * FEAT_DIM];
    __shared__ float s_FM[NUM_AA * FPAD];
    __shared__ float s_tbl[TBL];

    const int t = threadIdx.x;

    for (int k = t; k < NF; k += THREADS) {
        const int r = k >> 4, c = k & 15;
        s_F[r * FPAD + c] = features[k];
    }
    for (int k = t; k < FEAT_DIM * FEAT_DIM; k += THREADS) s_M[k] = M[k];
    __syncthreads();

    for (int k = t; k < NF; k += THREADS) {
        const int r = k >> 4, c = k & 15;
        float acc = 0.0f;
#pragma unroll
        for (int y = 0; y < FEAT_DIM; y++)
            acc = fmaf(s_F[r * FPAD + y], s_M[y * FEAT_DIM + c], acc);
        s_FM[r * FPAD + c] = acc;
    }
    __syncthreads();

    for (int e = t; e < TBL; e += THREADS) {
        const int i = e / NUM_AA;
        const int j = e % NUM_AA;
        float gii = 0.0f, gij = 0.0f, gji = 0.0f, gjj = 0.0f;
#pragma unroll
        for (int y = 0; y < FEAT_DIM; y++) {
            const float fiy  = s_F[i * FPAD + y];
            const float fjy  = s_F[j * FPAD + y];
            const float fmiy = s_FM[i * FPAD + y];
            const float fmjy = s_FM[j * FPAD + y];
            gii = fmaf(fmiy, fiy, gii);
            gij = fmaf(fmiy, fjy, gij);
            gji = fmaf(fmjy, fiy, gji);
            gjj = fmaf(fmjy, fjy, gjj);
        }
        s_tbl[e] = tanhf(gii - gij - gji + gjj);
    }
    __syncthreads();

    // ILP-2 batched gather: 4 independent LDG.128 in flight, tiny live set.
    const int stride = gridDim.x * THREADS;
    int p = blockIdx.x * THREADS + t;

    for (; p + stride < n4; p += 2 * stride) {
        int4 a0 = idx_i4[p];
        int4 a1 = idx_i4[p + stride];
        int4 b0 = idx_j4[p];
        int4 b1 = idx_j4[p + stride];
        float4 o;
        o.x = s_tbl[a0.x * NUM_AA + b0.x];
        o.y = s_tbl[a0.y * NUM_AA + b0.y];
        o.z = s_tbl[a0.z * NUM_AA + b0.z];
        o.w = s_tbl[a0.w * NUM_AA + b0.w];
        out4[p] = o;
        o.x = s_tbl[a1.x * NUM_AA + b1.x];
        o.y = s_tbl[a1.y * NUM_AA + b1.y];
        o.z = s_tbl[a1.z * NUM_AA + b1.z];
        o.w = s_tbl[a1.w * NUM_AA + b1.w];
        out4[p + stride] = o;
    }
    for (; p < n4; p += stride) {
        int4 a = idx_i4[p];
        int4 b = idx_j4[p];
        float4 o;
        o.x = s_tbl[a.x * NUM_AA + b.x];
        o.y = s_tbl[a.y * NUM_AA + b.y];
        o.z = s_tbl[a.z * NUM_AA + b.z];
        o.w = s_tbl[a.w * NUM_AA + b.w];
        out4[p] = o;
    }
}

extern "C" void kernel_launch(void* const* d_in, const int* in_sizes, int n_in,
                              void* d_out, int out_size)
{
    const float* features = (const float*)d_in[0];   // [20,16]
    const float* M        = (const float*)d_in[1];   // [16,16]
    const int*   idx_i    = (const int*)d_in[2];     // [P]
    const int*   idx_j    = (const int*)d_in[3];     // [P]
    float*       out      = (float*)d_out;           // [P]

    const int P  = out_size;   // 8,388,608
    const int n4 = P / 4;      // 2,097,152

    static int blocks = 0;
    if (blocks == 0) {
        int per_sm = 0;
        cudaOccupancyMaxActiveBlocksPerMultiprocessor(
            &per_sm, snack_fused_kernel, THREADS, 0);
        if (per_sm < 1) per_sm = 1;
        int sms = 0;
        cudaDeviceGetAttribute(&sms, cudaDevAttrMultiProcessorCount, 0);
        if (sms <= 0) sms = 148;
        blocks = per_sm * sms;
        int max_blocks = (n4 + THREADS - 1) / THREADS;
        if (blocks > max_blocks) blocks = max_blocks;
    }

    snack_fused_kernel<<<blocks, THREADS>>>(
        features, M,
        (const int4*)idx_i, (const int4*)idx_j,
        (float4*)out, n4);
}